// round 11
// baseline (speedup 1.0000x reference)
#include <cuda_runtime.h>
#include <cuda_bf16.h>
#include <cuda_fp16.h>

#define N_S 100000
#define N_C 20000
#define N_L 5000
#define E_U 2000000
#define E_T 500000
#define D_S 64
#define D_C 32
#define D_L 128
#define HDIM 128
#define NLAY 3

#define KAUG 328          // 128 (hc) + 200 (mf_aug)
#define MFW 200           // mf_aug row width: 192 feat + [1, mu, mt] + 5 pad

#define SCAN_ELEMS 1024
#define NBLK ((N_C + SCAN_ELEMS - 1) / SCAN_ELEMS)   // 20

// ---------------- scratch (static __device__ allocations only) ----------------
__device__ int    g_deg_u[N_C];
__device__ int    g_deg_t[N_C];
__device__ int    g_rp_u[N_C + 1];
__device__ int    g_rp_t[N_C + 1];
__device__ int    g_cur_u[N_C];
__device__ int    g_cur_t[N_C];
__device__ int    g_csr_u[E_U];
__device__ int    g_csr_t[E_T];
__device__ int    g_blksum[2][NBLK];
__device__ int    g_blkoff[2][NBLK];
__device__ float  g_mfa[N_C * MFW];            // augmented mf rows: [0:64)=mean_s, [64:192)=mean_l, [192]=1, [193]=mu, [194]=mt
__device__ float  g_Bcat[NLAY * KAUG * HDIM];  // per-layer concatenated B: [Ws_i ; Wfused slice ; bias rows ; zeros]
__device__ float  g_hcA[N_C * HDIM];
__device__ float  g_hcB[N_C * HDIM];
__device__ __half g_fs_h[N_S * D_S];           // fp16 copies of features (for L2-BW-bound agg)
__device__ __half g_fl_h[N_L * D_L];

// buffer tags (resolved on device)
#define TAG_EXT   0
#define TAG_HCA   4
#define TAG_HCB   5
#define TAG_BC    6

__device__ __forceinline__ const float* resolve_c(int tag, const float* ext, int off) {
    switch (tag) {
        case TAG_HCA: return g_hcA;
        case TAG_HCB: return g_hcB;
        case TAG_BC:  return g_Bcat + off;
        default:      return ext + off;
    }
}
__device__ __forceinline__ float* resolve_m(int tag, float* ext) {
    switch (tag) {
        case TAG_HCA: return g_hcA;
        case TAG_HCB: return g_hcB;
        default:      return ext;
    }
}

// ---------------- feature conversion to fp16 ----------------
__global__ void cvt_kernel(const float4* __restrict__ fs, const float4* __restrict__ fl) {
    int i = blockIdx.x * blockDim.x + threadIdx.x;
    const int nS = N_S * D_S / 4;
    const int nL = N_L * D_L / 4;
    if (i < nS) {
        float4 v = fs[i];
        __half2 h0 = __floats2half2_rn(v.x, v.y);
        __half2 h1 = __floats2half2_rn(v.z, v.w);
        ((__half2*)g_fs_h)[i * 2 + 0] = h0;
        ((__half2*)g_fs_h)[i * 2 + 1] = h1;
    } else {
        int j = i - nS;
        if (j < nL) {
            float4 v = fl[j];
            __half2 h0 = __floats2half2_rn(v.x, v.y);
            __half2 h1 = __floats2half2_rn(v.z, v.w);
            ((__half2*)g_fl_h)[j * 2 + 0] = h0;
            ((__half2*)g_fl_h)[j * 2 + 1] = h1;
        }
    }
}

// ---------------- CSR build ----------------
__global__ void zero_deg_kernel() {
    int i = blockIdx.x * blockDim.x + threadIdx.x;
    if (i < N_C) { g_deg_u[i] = 0; g_deg_t[i] = 0; }
}

__global__ void hist_all_kernel(const int4* __restrict__ und_dst, const int4* __restrict__ tea_dst) {
    int i = blockIdx.x * blockDim.x + threadIdx.x;
    if (i < E_U / 4) {
        int4 d = und_dst[i];
        atomicAdd(&g_deg_u[d.x], 1);
        atomicAdd(&g_deg_u[d.y], 1);
        atomicAdd(&g_deg_u[d.z], 1);
        atomicAdd(&g_deg_u[d.w], 1);
    } else {
        int j = i - E_U / 4;
        if (j < E_T / 4) {
            int4 d = tea_dst[j];
            atomicAdd(&g_deg_t[d.x], 1);
            atomicAdd(&g_deg_t[d.y], 1);
            atomicAdd(&g_deg_t[d.z], 1);
            atomicAdd(&g_deg_t[d.w], 1);
        }
    }
}

__global__ void scan_part_kernel() {
    int rel = blockIdx.y;
    const int* deg = rel ? g_deg_t : g_deg_u;
    int tid = threadIdx.x;
    int base = blockIdx.x * SCAN_ELEMS + tid * 4;
    int s = 0;
#pragma unroll
    for (int j = 0; j < 4; j++)
        if (base + j < N_C) s += deg[base + j];
    __shared__ int sh[256];
    sh[tid] = s;
    __syncthreads();
    for (int off = 128; off > 0; off >>= 1) {
        if (tid < off) sh[tid] += sh[tid + off];
        __syncthreads();
    }
    if (tid == 0) g_blksum[rel][blockIdx.x] = sh[0];
}

__global__ void scan_mid_kernel() {
    int tid = threadIdx.x;
    if (tid < 2) {
        int run = 0;
        for (int b = 0; b < NBLK; b++) {
            g_blkoff[tid][b] = run;
            run += g_blksum[tid][b];
        }
        if (tid) g_rp_t[N_C] = run; else g_rp_u[N_C] = run;
    }
}

// phase 3: emit rowptr + cur + mf_aug flag columns
__global__ void scan_emit_kernel() {
    int rel = blockIdx.y;
    const int* deg = rel ? g_deg_t : g_deg_u;
    int* rowptr = rel ? g_rp_t : g_rp_u;
    int* cur = rel ? g_cur_t : g_cur_u;
    int tid = threadIdx.x;
    int base = blockIdx.x * SCAN_ELEMS + tid * 4;
    int v[4];
    int s = 0;
#pragma unroll
    for (int j = 0; j < 4; j++) {
        v[j] = (base + j < N_C) ? deg[base + j] : 0;
        s += v[j];
    }
    __shared__ int sh[256];
    sh[tid] = s;
    __syncthreads();
    for (int off = 1; off < 256; off <<= 1) {
        int t = (tid >= off) ? sh[tid - off] : 0;
        __syncthreads();
        sh[tid] += t;
        __syncthreads();
    }
    int excl = ((tid > 0) ? sh[tid - 1] : 0) + g_blkoff[rel][blockIdx.x];
#pragma unroll
    for (int j = 0; j < 4; j++) {
        int i = base + j;
        if (i < N_C) {
            rowptr[i] = excl;
            cur[i] = excl;
            excl += v[j];
            float* mr = g_mfa + (size_t)i * MFW;
            if (rel == 0) {
                mr[192] = 1.0f;
                mr[193] = (v[j] > 0) ? 1.0f : 0.0f;
                mr[195] = 0.f; mr[196] = 0.f; mr[197] = 0.f; mr[198] = 0.f; mr[199] = 0.f;
            } else {
                mr[194] = (v[j] > 0) ? 1.0f : 0.0f;
            }
        }
    }
}

__global__ void scatter_all_kernel(const int4* __restrict__ und_src, const int4* __restrict__ und_dst,
                                   const int4* __restrict__ tea_src, const int4* __restrict__ tea_dst) {
    int i = blockIdx.x * blockDim.x + threadIdx.x;
    if (i < E_U / 4) {
        int4 d = und_dst[i];
        int4 s = und_src[i];
        g_csr_u[atomicAdd(&g_cur_u[d.x], 1)] = s.x;
        g_csr_u[atomicAdd(&g_cur_u[d.y], 1)] = s.y;
        g_csr_u[atomicAdd(&g_cur_u[d.z], 1)] = s.z;
        g_csr_u[atomicAdd(&g_cur_u[d.w], 1)] = s.w;
    } else {
        int j = i - E_U / 4;
        if (j < E_T / 4) {
            int4 d = tea_dst[j];
            int4 s = tea_src[j];
            g_csr_t[atomicAdd(&g_cur_t[d.x], 1)] = s.x;
            g_csr_t[atomicAdd(&g_cur_t[d.y], 1)] = s.y;
            g_csr_t[atomicAdd(&g_cur_t[d.z], 1)] = s.z;
            g_csr_t[atomicAdd(&g_cur_t[d.w], 1)] = s.w;
        }
    }
}

// ---------------- aggregation on fp16 features (halved L2 traffic) ----------------
__global__ void agg_all_kernel() {
    int w = (blockIdx.x * blockDim.x + threadIdx.x) >> 5;
    int lane = threadIdx.x & 31;
    if (w < N_C) {
        // student: 64 halves/row = one __half2 per lane (128B line per edge)
        int s0 = g_rp_u[w], s1 = g_rp_u[w + 1];
        float2 a0 = {0.f, 0.f}, a1 = {0.f, 0.f}, a2 = {0.f, 0.f}, a3 = {0.f, 0.f};
        int e = s0;
        for (; e + 4 <= s1; e += 4) {
            int i0 = g_csr_u[e], i1 = g_csr_u[e + 1], i2 = g_csr_u[e + 2], i3 = g_csr_u[e + 3];
            __half2 h0 = ((const __half2*)(g_fs_h + (size_t)i0 * D_S))[lane];
            __half2 h1 = ((const __half2*)(g_fs_h + (size_t)i1 * D_S))[lane];
            __half2 h2 = ((const __half2*)(g_fs_h + (size_t)i2 * D_S))[lane];
            __half2 h3 = ((const __half2*)(g_fs_h + (size_t)i3 * D_S))[lane];
            float2 v0 = __half22float2(h0), v1 = __half22float2(h1);
            float2 v2 = __half22float2(h2), v3 = __half22float2(h3);
            a0.x += v0.x; a0.y += v0.y;
            a1.x += v1.x; a1.y += v1.y;
            a2.x += v2.x; a2.y += v2.y;
            a3.x += v3.x; a3.y += v3.y;
        }
        for (; e < s1; e++) {
            int i0 = g_csr_u[e];
            float2 v0 = __half22float2(((const __half2*)(g_fs_h + (size_t)i0 * D_S))[lane]);
            a0.x += v0.x; a0.y += v0.y;
        }
        float sx = a0.x + a1.x + a2.x + a3.x;
        float sy = a0.y + a1.y + a2.y + a3.y;
        float inv = 1.0f / (float)max(s1 - s0, 1);
        g_mfa[(size_t)w * MFW + lane * 2 + 0] = sx * inv;
        g_mfa[(size_t)w * MFW + lane * 2 + 1] = sy * inv;
    } else if (w < 2 * N_C) {
        // lecture: 128 halves/row = uint2 (2x half2) per lane (256B per edge)
        int c = w - N_C;
        int s0 = g_rp_t[c], s1 = g_rp_t[c + 1];
        float4 a0 = {0, 0, 0, 0}, a1 = {0, 0, 0, 0};
        int e = s0;
        for (; e + 2 <= s1; e += 2) {
            int i0 = g_csr_t[e], i1 = g_csr_t[e + 1];
            uint2 u0 = ((const uint2*)(g_fl_h + (size_t)i0 * D_L))[lane];
            uint2 u1 = ((const uint2*)(g_fl_h + (size_t)i1 * D_L))[lane];
            float2 p0 = __half22float2(*(__half2*)&u0.x);
            float2 p1 = __half22float2(*(__half2*)&u0.y);
            float2 q0 = __half22float2(*(__half2*)&u1.x);
            float2 q1 = __half22float2(*(__half2*)&u1.y);
            a0.x += p0.x; a0.y += p0.y; a0.z += p1.x; a0.w += p1.y;
            a1.x += q0.x; a1.y += q0.y; a1.z += q1.x; a1.w += q1.y;
        }
        for (; e < s1; e++) {
            int i0 = g_csr_t[e];
            uint2 u0 = ((const uint2*)(g_fl_h + (size_t)i0 * D_L))[lane];
            float2 p0 = __half22float2(*(__half2*)&u0.x);
            float2 p1 = __half22float2(*(__half2*)&u0.y);
            a0.x += p0.x; a0.y += p0.y; a0.z += p1.x; a0.w += p1.y;
        }
        float sx = a0.x + a1.x, sy = a0.y + a1.y, sz = a0.z + a1.z, sw = a0.w + a1.w;
        float inv = 1.0f / (float)max(s1 - s0, 1);
        float* o = g_mfa + (size_t)c * MFW + 64 + lane * 4;
        o[0] = sx * inv; o[1] = sy * inv; o[2] = sz * inv; o[3] = sw * inv;
    }
}

// ---------------- weight prep: build g_Bcat[li][KAUG][128] ----------------
// rows 0..127   : W_self_u[li] + W_self_t[li]
// rows 128..191 : W_fs @ W_neigh_u[li]          (mean_s path)
// rows 192..319 : W_fl @ W_neigh_t[li]          (mean_l path)
// row  320      : b_u[li] + b_t[li]             (pairs with mfa[192]=1)
// row  321      : b_fs @ W_neigh_u[li]          (pairs with mfa[193]=mu)
// row  322      : b_fl @ W_neigh_t[li]          (pairs with mfa[194]=mt)
// rows 323..327 : 0
__global__ void prep_kernel(const float* __restrict__ W_fs, const float* __restrict__ b_fs,
                            const float* __restrict__ W_fl, const float* __restrict__ b_fl,
                            const float* __restrict__ Wsu, const float* __restrict__ Wnu,
                            const float* __restrict__ bu_in,
                            const float* __restrict__ Wst, const float* __restrict__ Wnt,
                            const float* __restrict__ bt_in) {
    int idx = blockIdx.x * blockDim.x + threadIdx.x;
    const int per = KAUG * HDIM;
    if (idx >= NLAY * per) return;
    int li = idx / per;
    int rem = idx - li * per;
    int k = rem >> 7;        // 0..327
    int n = rem & 127;
    float v;
    if (k < 128) {
        v = Wsu[li * 16384 + k * 128 + n] + Wst[li * 16384 + k * 128 + n];
    } else {
        int r = k - 128;     // 0..199
        if (r < 64) {
            const float* wn = Wnu + li * 16384;
            float s = 0.f;
            for (int j = 0; j < 128; j++) s += W_fs[r * 128 + j] * wn[j * 128 + n];
            v = s;
        } else if (r < 192) {
            const float* wn = Wnt + li * 16384;
            int rr = r - 64;
            float s = 0.f;
            for (int j = 0; j < 128; j++) s += W_fl[rr * 128 + j] * wn[j * 128 + n];
            v = s;
        } else if (r == 192) {
            v = bu_in[li * 128 + n] + bt_in[li * 128 + n];
        } else if (r == 193) {
            const float* wn = Wnu + li * 16384;
            float s = 0.f;
            for (int j = 0; j < 128; j++) s += b_fs[j] * wn[j * 128 + n];
            v = s;
        } else if (r == 194) {
            const float* wn = Wnt + li * 16384;
            float s = 0.f;
            for (int j = 0; j < 128; j++) s += b_fl[j] * wn[j * 128 + n];
            v = s;
        } else {
            v = 0.f;
        }
    }
    g_Bcat[li * per + k * 128 + n] = v;
}

// ---------------- tiled SIMT GEMM: 128x64 tile, 8x4/thread (proven config) ----------------
// aug=1: A = [hc(128) | g_mfa(200)] per row, K=KAUG.  epi_mode: 0 = alpha+relu, 2 = +bias
__global__ __launch_bounds__(256) void gemm_kernel(
    int a_tag, const float* a_ext, int lda, int aug,
    int b_tag, const float* b_ext, int b_off, int ldb,
    int c_tag, float* c_ext, int ldc,
    int M, int N, int K,
    int epi_mode, const float* bias_ext,
    float alpha, int relu) {
    const float* A = resolve_c(a_tag, a_ext, 0);
    const float* B = resolve_c(b_tag, b_ext, b_off);
    float* C = resolve_m(c_tag, c_ext);

    __shared__ float As[8][132];
    __shared__ float Bs[8][68];
    int tid = threadIdx.x;
    int m0 = blockIdx.x * 128;
    int n0 = blockIdx.y * 64;
    int tx = tid & 15;
    int ty = tid >> 4;

    float acc[8][4];
#pragma unroll
    for (int i = 0; i < 8; i++)
#pragma unroll
        for (int j = 0; j < 4; j++) acc[i][j] = 0.f;

    int la_row = tid >> 1;
    int la_k = (tid & 1) * 4;
    int lb_k = tid >> 5;
    int lb_n = (tid & 31) * 2;

    for (int k0 = 0; k0 < K; k0 += 8) {
        float4 av = {0.f, 0.f, 0.f, 0.f};
        int gm = m0 + la_row;
        if (gm < M) {
            int kk = k0 + la_k;
            if (!aug) {
                av = *(const float4*)(A + (size_t)gm * lda + kk);
            } else if (kk < 128) {
                av = *(const float4*)(A + (size_t)gm * 128 + kk);
            } else {
                av = *(const float4*)(g_mfa + (size_t)gm * MFW + (kk - 128));
            }
        }
        As[la_k + 0][la_row] = av.x;
        As[la_k + 1][la_row] = av.y;
        As[la_k + 2][la_row] = av.z;
        As[la_k + 3][la_row] = av.w;
        float2 bv = *(const float2*)(B + (size_t)(k0 + lb_k) * ldb + n0 + lb_n);
        Bs[lb_k][lb_n] = bv.x;
        Bs[lb_k][lb_n + 1] = bv.y;
        __syncthreads();
#pragma unroll
        for (int kk = 0; kk < 8; kk++) {
            float4 a0 = *(const float4*)&As[kk][ty * 8];
            float4 a1 = *(const float4*)&As[kk][ty * 8 + 4];
            float4 b = *(const float4*)&Bs[kk][tx * 4];
            float a[8] = {a0.x, a0.y, a0.z, a0.w, a1.x, a1.y, a1.z, a1.w};
            float bb[4] = {b.x, b.y, b.z, b.w};
#pragma unroll
            for (int i = 0; i < 8; i++)
#pragma unroll
                for (int j = 0; j < 4; j++) acc[i][j] += a[i] * bb[j];
        }
        __syncthreads();
    }

#pragma unroll
    for (int i = 0; i < 8; i++) {
        int gm = m0 + ty * 8 + i;
        if (gm >= M) break;
        float res[4];
#pragma unroll
        for (int j = 0; j < 4; j++) {
            int gn = n0 + tx * 4 + j;
            float v = acc[i][j];
            if (epi_mode == 2) v += bias_ext[gn];
            v *= alpha;
            if (relu) v = fmaxf(v, 0.f);
            res[j] = v;
        }
        *(float4*)(C + (size_t)gm * ldc + n0 + tx * 4) = make_float4(res[0], res[1], res[2], res[3]);
    }
}

// ---------------- launch (pure kernel launches; no other CUDA API) ----------------
extern "C" void kernel_launch(void* const* d_in, const int* in_sizes, int n_in,
                              void* d_out, int out_size) {
    const float* feat_s = (const float*)d_in[0];
    const float* feat_c = (const float*)d_in[1];
    const float* feat_l = (const float*)d_in[2];
    const float* W_fs = (const float*)d_in[3];
    const float* b_fs = (const float*)d_in[4];
    const float* W_fc = (const float*)d_in[5];
    const float* b_fc = (const float*)d_in[6];
    const float* W_fl = (const float*)d_in[7];
    const float* b_fl = (const float*)d_in[8];
    const float* W_self_u = (const float*)d_in[9];
    const float* W_neigh_u = (const float*)d_in[10];
    const float* b_u = (const float*)d_in[11];
    const float* W_self_t = (const float*)d_in[12];
    const float* W_neigh_t = (const float*)d_in[13];
    const float* b_t = (const float*)d_in[14];
    const int* und_src = (const int*)d_in[15];
    const int* und_dst = (const int*)d_in[16];
    const int* tea_src = (const int*)d_in[17];
    const int* tea_dst = (const int*)d_in[18];
    float* out = (float*)d_out;

    // independent prep first
    zero_deg_kernel<<<(N_C + 255) / 256, 256>>>();
    {
        int total = (N_S * D_S + N_L * D_L) / 4;
        cvt_kernel<<<(total + 255) / 256, 256>>>((const float4*)feat_s, (const float4*)feat_l);
    }
    prep_kernel<<<(NLAY * KAUG * HDIM + 255) / 256, 256>>>(W_fs, b_fs, W_fl, b_fl,
                                                           W_self_u, W_neigh_u, b_u,
                                                           W_self_t, W_neigh_t, b_t);

    // CSR build
    hist_all_kernel<<<((E_U + E_T) / 4 + 255) / 256, 256>>>((const int4*)und_dst, (const int4*)tea_dst);
    {
        dim3 g(NBLK, 2);
        scan_part_kernel<<<g, 256>>>();
        scan_mid_kernel<<<1, 32>>>();
        // proj (independent of CSR): hcA = feat_c @ W_fc + b_fc
        {
            dim3 grid((N_C + 127) / 128, HDIM / 64);
            gemm_kernel<<<grid, 256>>>(TAG_EXT, feat_c, D_C, /*aug*/0,
                                       TAG_EXT, W_fc, 0, HDIM,
                                       TAG_HCA, nullptr, HDIM,
                                       N_C, HDIM, D_C,
                                       /*epi*/2, b_fc, 1.f, 0);
        }
        scan_emit_kernel<<<g, 256>>>();
    }
    scatter_all_kernel<<<((E_U + E_T) / 4 + 255) / 256, 256>>>(
        (const int4*)und_src, (const int4*)und_dst, (const int4*)tea_src, (const int4*)tea_dst);

    // segment means of fp16 features into g_mfa
    agg_all_kernel<<<(2 * N_C * 32 + 255) / 256, 256>>>();

    // three layers: hc_next = act(alpha_i * ([hc | mf_aug] @ Bcat_i))
    for (int li = 0; li < NLAY; li++) {
        int a_tag = (li & 1) ? TAG_HCB : TAG_HCA;
        int c_tag = (li == NLAY - 1) ? TAG_EXT : ((li & 1) ? TAG_HCA : TAG_HCB);
        float* c_ext = (li == NLAY - 1) ? out : nullptr;
        float alpha = (li == 0) ? 0.5f : 1.0f;
        int relu = (li < NLAY - 1) ? 1 : 0;
        dim3 grid((N_C + 127) / 128, HDIM / 64);
        gemm_kernel<<<grid, 256>>>(a_tag, nullptr, HDIM, /*aug*/1,
                                   TAG_BC, nullptr, li * KAUG * HDIM, HDIM,
                                   c_tag, c_ext, HDIM,
                                   N_C, HDIM, KAUG,
                                   /*epi*/0, nullptr, alpha, relu);
    }
}

// round 12
// speedup vs baseline: 1.0867x; 1.0867x over previous
#include <cuda_runtime.h>
#include <cuda_bf16.h>
#include <cuda_fp16.h>

#define N_S 100000
#define N_C 20000
#define N_L 5000
#define E_U 2000000
#define E_T 500000
#define D_S 64
#define D_C 32
#define D_L 128
#define HDIM 128
#define NLAY 3

#define SCAN_ELEMS 1024
#define NBLK ((N_C + SCAN_ELEMS - 1) / SCAN_ELEMS)   // 20

// ---------------- scratch (static __device__ allocations only) ----------------
__device__ int    g_deg_u[N_C];
__device__ int    g_deg_t[N_C];
__device__ int    g_rp_u[N_C + 1];
__device__ int    g_rp_t[N_C + 1];
__device__ int    g_cur_u[N_C];
__device__ int    g_cur_t[N_C];
__device__ int    g_csr_u[E_U];
__device__ int    g_csr_t[E_T];
__device__ int    g_blksum[2][NBLK];
__device__ int    g_blkoff[2][NBLK];
__device__ float  g_mf[N_C * 192];        // [c][0:64]=mean student feat, [64:192]=mean lecture feat
__device__ float  g_Wfused[192 * 384];    // rows 0:64 = W_fs@Wnu_i ; rows 64:192 = W_fl@Wnt_i
__device__ float  g_bu[384];              // b_fs @ Wnu_i  (applies when deg_u>0)
__device__ float  g_bl[384];              // b_fl @ Wnt_i  (applies when deg_t>0)
__device__ float  g_bsum[384];            // b_u[i] + b_t[i]
__device__ float  g_Ws[NLAY * HDIM * HDIM];   // W_self_u[i] + W_self_t[i]
__device__ float  g_const[N_C * 384];     // per-layer constant terms
__device__ float  g_hcA[N_C * HDIM];
__device__ float  g_hcB[N_C * HDIM];
__device__ __half g_fs_h[N_S * D_S];      // fp16 feature copies (halved agg L2 traffic)
__device__ __half g_fl_h[N_L * D_L];

// buffer tags (resolved on device; keeps kernel_launch free of cudaGetSymbolAddress)
#define TAG_EXT   0
#define TAG_MF    1
#define TAG_WF    2
#define TAG_CONST 3
#define TAG_HCA   4
#define TAG_HCB   5
#define TAG_WS    6

__device__ __forceinline__ const float* resolve_c(int tag, const float* ext, int off) {
    switch (tag) {
        case TAG_MF:    return g_mf;
        case TAG_WF:    return g_Wfused;
        case TAG_CONST: return g_const;
        case TAG_HCA:   return g_hcA;
        case TAG_HCB:   return g_hcB;
        case TAG_WS:    return g_Ws + off;
        default:        return ext + off;
    }
}
__device__ __forceinline__ float* resolve_m(int tag, float* ext) {
    switch (tag) {
        case TAG_CONST: return g_const;
        case TAG_HCA:   return g_hcA;
        case TAG_HCB:   return g_hcB;
        default:        return ext;
    }
}

// ---------------- feature conversion to fp16 ----------------
__global__ void cvt_kernel(const float4* __restrict__ fs, const float4* __restrict__ fl) {
    int i = blockIdx.x * blockDim.x + threadIdx.x;
    const int nS = N_S * D_S / 4;
    const int nL = N_L * D_L / 4;
    if (i < nS) {
        float4 v = fs[i];
        ((__half2*)g_fs_h)[i * 2 + 0] = __floats2half2_rn(v.x, v.y);
        ((__half2*)g_fs_h)[i * 2 + 1] = __floats2half2_rn(v.z, v.w);
    } else {
        int j = i - nS;
        if (j < nL) {
            float4 v = fl[j];
            ((__half2*)g_fl_h)[j * 2 + 0] = __floats2half2_rn(v.x, v.y);
            ((__half2*)g_fl_h)[j * 2 + 1] = __floats2half2_rn(v.z, v.w);
        }
    }
}

// ---------------- CSR build ----------------
__global__ void zero_deg_kernel() {
    int i = blockIdx.x * blockDim.x + threadIdx.x;
    if (i < N_C) { g_deg_u[i] = 0; g_deg_t[i] = 0; }
}

__global__ void hist_all_kernel(const int4* __restrict__ und_dst, const int4* __restrict__ tea_dst) {
    int i = blockIdx.x * blockDim.x + threadIdx.x;
    if (i < E_U / 4) {
        int4 d = und_dst[i];
        atomicAdd(&g_deg_u[d.x], 1);
        atomicAdd(&g_deg_u[d.y], 1);
        atomicAdd(&g_deg_u[d.z], 1);
        atomicAdd(&g_deg_u[d.w], 1);
    } else {
        int j = i - E_U / 4;
        if (j < E_T / 4) {
            int4 d = tea_dst[j];
            atomicAdd(&g_deg_t[d.x], 1);
            atomicAdd(&g_deg_t[d.y], 1);
            atomicAdd(&g_deg_t[d.z], 1);
            atomicAdd(&g_deg_t[d.w], 1);
        }
    }
}

__global__ void scan_part_kernel() {
    int rel = blockIdx.y;
    const int* deg = rel ? g_deg_t : g_deg_u;
    int tid = threadIdx.x;
    int base = blockIdx.x * SCAN_ELEMS + tid * 4;
    int s = 0;
#pragma unroll
    for (int j = 0; j < 4; j++)
        if (base + j < N_C) s += deg[base + j];
    __shared__ int sh[256];
    sh[tid] = s;
    __syncthreads();
    for (int off = 128; off > 0; off >>= 1) {
        if (tid < off) sh[tid] += sh[tid + off];
        __syncthreads();
    }
    if (tid == 0) g_blksum[rel][blockIdx.x] = sh[0];
}

__global__ void scan_mid_kernel() {
    int tid = threadIdx.x;
    if (tid < 2) {
        int run = 0;
        for (int b = 0; b < NBLK; b++) {
            g_blkoff[tid][b] = run;
            run += g_blksum[tid][b];
        }
        if (tid) g_rp_t[N_C] = run; else g_rp_u[N_C] = run;
    }
}

__global__ void scan_emit_kernel() {
    int rel = blockIdx.y;
    const int* deg = rel ? g_deg_t : g_deg_u;
    int* rowptr = rel ? g_rp_t : g_rp_u;
    int* cur = rel ? g_cur_t : g_cur_u;
    int tid = threadIdx.x;
    int base = blockIdx.x * SCAN_ELEMS + tid * 4;
    int v[4];
    int s = 0;
#pragma unroll
    for (int j = 0; j < 4; j++) {
        v[j] = (base + j < N_C) ? deg[base + j] : 0;
        s += v[j];
    }
    __shared__ int sh[256];
    sh[tid] = s;
    __syncthreads();
    for (int off = 1; off < 256; off <<= 1) {
        int t = (tid >= off) ? sh[tid - off] : 0;
        __syncthreads();
        sh[tid] += t;
        __syncthreads();
    }
    int excl = ((tid > 0) ? sh[tid - 1] : 0) + g_blkoff[rel][blockIdx.x];
#pragma unroll
    for (int j = 0; j < 4; j++) {
        if (base + j < N_C) {
            rowptr[base + j] = excl;
            cur[base + j] = excl;
            excl += v[j];
        }
    }
}

__global__ void scatter_all_kernel(const int4* __restrict__ und_src, const int4* __restrict__ und_dst,
                                   const int4* __restrict__ tea_src, const int4* __restrict__ tea_dst) {
    int i = blockIdx.x * blockDim.x + threadIdx.x;
    if (i < E_U / 4) {
        int4 d = und_dst[i];
        int4 s = und_src[i];
        g_csr_u[atomicAdd(&g_cur_u[d.x], 1)] = s.x;
        g_csr_u[atomicAdd(&g_cur_u[d.y], 1)] = s.y;
        g_csr_u[atomicAdd(&g_cur_u[d.z], 1)] = s.z;
        g_csr_u[atomicAdd(&g_cur_u[d.w], 1)] = s.w;
    } else {
        int j = i - E_U / 4;
        if (j < E_T / 4) {
            int4 d = tea_dst[j];
            int4 s = tea_src[j];
            g_csr_t[atomicAdd(&g_cur_t[d.x], 1)] = s.x;
            g_csr_t[atomicAdd(&g_cur_t[d.y], 1)] = s.y;
            g_csr_t[atomicAdd(&g_cur_t[d.z], 1)] = s.z;
            g_csr_t[atomicAdd(&g_cur_t[d.w], 1)] = s.w;
        }
    }
}

// ---------------- aggregation on fp16 features (halved L2 traffic) ----------------
__global__ void agg_all_kernel() {
    int w = (blockIdx.x * blockDim.x + threadIdx.x) >> 5;
    int lane = threadIdx.x & 31;
    if (w < N_C) {
        // student: 64 halves/row -> one __half2 per lane (one 128B line per edge)
        int s0 = g_rp_u[w], s1 = g_rp_u[w + 1];
        float2 a0 = {0.f, 0.f}, a1 = {0.f, 0.f}, a2 = {0.f, 0.f}, a3 = {0.f, 0.f};
        int e = s0;
        for (; e + 4 <= s1; e += 4) {
            int i0 = g_csr_u[e], i1 = g_csr_u[e + 1], i2 = g_csr_u[e + 2], i3 = g_csr_u[e + 3];
            float2 v0 = __half22float2(((const __half2*)(g_fs_h + (size_t)i0 * D_S))[lane]);
            float2 v1 = __half22float2(((const __half2*)(g_fs_h + (size_t)i1 * D_S))[lane]);
            float2 v2 = __half22float2(((const __half2*)(g_fs_h + (size_t)i2 * D_S))[lane]);
            float2 v3 = __half22float2(((const __half2*)(g_fs_h + (size_t)i3 * D_S))[lane]);
            a0.x += v0.x; a0.y += v0.y;
            a1.x += v1.x; a1.y += v1.y;
            a2.x += v2.x; a2.y += v2.y;
            a3.x += v3.x; a3.y += v3.y;
        }
        for (; e < s1; e++) {
            int i0 = g_csr_u[e];
            float2 v0 = __half22float2(((const __half2*)(g_fs_h + (size_t)i0 * D_S))[lane]);
            a0.x += v0.x; a0.y += v0.y;
        }
        float sx = a0.x + a1.x + a2.x + a3.x;
        float sy = a0.y + a1.y + a2.y + a3.y;
        float inv = 1.0f / (float)max(s1 - s0, 1);
        g_mf[(size_t)w * 192 + lane * 2 + 0] = sx * inv;
        g_mf[(size_t)w * 192 + lane * 2 + 1] = sy * inv;
    } else if (w < 2 * N_C) {
        // lecture: 128 halves/row -> uint2 (2x half2) per lane (256B per edge)
        int c = w - N_C;
        int s0 = g_rp_t[c], s1 = g_rp_t[c + 1];
        float4 a0 = {0, 0, 0, 0}, a1 = {0, 0, 0, 0};
        int e = s0;
        for (; e + 2 <= s1; e += 2) {
            int i0 = g_csr_t[e], i1 = g_csr_t[e + 1];
            uint2 u0 = ((const uint2*)(g_fl_h + (size_t)i0 * D_L))[lane];
            uint2 u1 = ((const uint2*)(g_fl_h + (size_t)i1 * D_L))[lane];
            float2 p0 = __half22float2(*(__half2*)&u0.x);
            float2 p1 = __half22float2(*(__half2*)&u0.y);
            float2 q0 = __half22float2(*(__half2*)&u1.x);
            float2 q1 = __half22float2(*(__half2*)&u1.y);
            a0.x += p0.x; a0.y += p0.y; a0.z += p1.x; a0.w += p1.y;
            a1.x += q0.x; a1.y += q0.y; a1.z += q1.x; a1.w += q1.y;
        }
        for (; e < s1; e++) {
            int i0 = g_csr_t[e];
            uint2 u0 = ((const uint2*)(g_fl_h + (size_t)i0 * D_L))[lane];
            float2 p0 = __half22float2(*(__half2*)&u0.x);
            float2 p1 = __half22float2(*(__half2*)&u0.y);
            a0.x += p0.x; a0.y += p0.y; a0.z += p1.x; a0.w += p1.y;
        }
        float sx = a0.x + a1.x, sy = a0.y + a1.y, sz = a0.z + a1.z, sw = a0.w + a1.w;
        float inv = 1.0f / (float)max(s1 - s0, 1);
        float* o = g_mf + (size_t)c * 192 + 64 + lane * 4;
        o[0] = sx * inv; o[1] = sy * inv; o[2] = sz * inv; o[3] = sw * inv;
    }
}

// ---------------- fused weight prep (tiny; R10-identical) ----------------
__global__ void prep_kernel(const float* __restrict__ W_fs, const float* __restrict__ b_fs,
                            const float* __restrict__ W_fl, const float* __restrict__ b_fl,
                            const float* __restrict__ Wsu, const float* __restrict__ Wnu,
                            const float* __restrict__ bu_in,
                            const float* __restrict__ Wst, const float* __restrict__ Wnt,
                            const float* __restrict__ bt_in) {
    const int n0 = 64 * 384;
    const int n1 = 128 * 384;
    const int n2 = 384, n3 = 384, n4 = 384;
    const int n5 = NLAY * HDIM * HDIM;
    int idx = blockIdx.x * blockDim.x + threadIdx.x;
    if (idx < n0) {
        int r = idx / 384, c = idx % 384;
        int li = c >> 7, n = c & 127;
        const float* wn = Wnu + li * HDIM * HDIM;
        float s = 0.f;
        for (int k = 0; k < HDIM; k++) s += W_fs[r * HDIM + k] * wn[k * HDIM + n];
        g_Wfused[r * 384 + c] = s;
        return;
    }
    idx -= n0;
    if (idx < n1) {
        int r = idx / 384, c = idx % 384;
        int li = c >> 7, n = c & 127;
        const float* wn = Wnt + li * HDIM * HDIM;
        float s = 0.f;
        for (int k = 0; k < HDIM; k++) s += W_fl[r * HDIM + k] * wn[k * HDIM + n];
        g_Wfused[(64 + r) * 384 + c] = s;
        return;
    }
    idx -= n1;
    if (idx < n2) {
        int li = idx >> 7, n = idx & 127;
        const float* wn = Wnu + li * HDIM * HDIM;
        float s = 0.f;
        for (int k = 0; k < HDIM; k++) s += b_fs[k] * wn[k * HDIM + n];
        g_bu[idx] = s;
        return;
    }
    idx -= n2;
    if (idx < n3) {
        int li = idx >> 7, n = idx & 127;
        const float* wn = Wnt + li * HDIM * HDIM;
        float s = 0.f;
        for (int k = 0; k < HDIM; k++) s += b_fl[k] * wn[k * HDIM + n];
        g_bl[idx] = s;
        return;
    }
    idx -= n3;
    if (idx < n4) {
        g_bsum[idx] = bu_in[idx] + bt_in[idx];
        return;
    }
    idx -= n4;
    if (idx < n5) {
        g_Ws[idx] = Wsu[idx] + Wst[idx];
        return;
    }
}

// ---------------- tiled SIMT GEMM (R10-identical): 128x64 tile, 8x4/thread ----------------
__global__ __launch_bounds__(256) void gemm_kernel(
    int a_tag, const float* a_ext, int lda,
    int b_tag, const float* b_ext, int b_off, int ldb,
    int c_tag, float* c_ext, int ldc,
    int M, int N, int K,
    int epi_mode, const float* bias_ext,
    int use_cbuf, int coff,
    float alpha, int relu) {
    const float* A = resolve_c(a_tag, a_ext, 0);
    const float* B = resolve_c(b_tag, b_ext, b_off);
    float* C = resolve_m(c_tag, c_ext);

    __shared__ float As[8][132];
    __shared__ float Bs[8][68];
    int tid = threadIdx.x;
    int m0 = blockIdx.x * 128;
    int n0 = blockIdx.y * 64;
    int tx = tid & 15;
    int ty = tid >> 4;

    float acc[8][4];
#pragma unroll
    for (int i = 0; i < 8; i++)
#pragma unroll
        for (int j = 0; j < 4; j++) acc[i][j] = 0.f;

    int la_row = tid >> 1;
    int la_k = (tid & 1) * 4;
    int lb_k = tid >> 5;
    int lb_n = (tid & 31) * 2;

    for (int k0 = 0; k0 < K; k0 += 8) {
        float4 av = {0.f, 0.f, 0.f, 0.f};
        int gm = m0 + la_row;
        if (gm < M) av = *(const float4*)(A + (size_t)gm * lda + k0 + la_k);
        As[la_k + 0][la_row] = av.x;
        As[la_k + 1][la_row] = av.y;
        As[la_k + 2][la_row] = av.z;
        As[la_k + 3][la_row] = av.w;
        float2 bv = *(const float2*)(B + (size_t)(k0 + lb_k) * ldb + n0 + lb_n);
        Bs[lb_k][lb_n] = bv.x;
        Bs[lb_k][lb_n + 1] = bv.y;
        __syncthreads();
#pragma unroll
        for (int kk = 0; kk < 8; kk++) {
            float4 a0 = *(const float4*)&As[kk][ty * 8];
            float4 a1 = *(const float4*)&As[kk][ty * 8 + 4];
            float4 b = *(const float4*)&Bs[kk][tx * 4];
            float a[8] = {a0.x, a0.y, a0.z, a0.w, a1.x, a1.y, a1.z, a1.w};
            float bb[4] = {b.x, b.y, b.z, b.w};
#pragma unroll
            for (int i = 0; i < 8; i++)
#pragma unroll
                for (int j = 0; j < 4; j++) acc[i][j] += a[i] * bb[j];
        }
        __syncthreads();
    }

#pragma unroll
    for (int i = 0; i < 8; i++) {
        int gm = m0 + ty * 8 + i;
        if (gm >= M) break;
        bool mu = false, mt = false;
        if (epi_mode == 1) {
            mu = (g_deg_u[gm] > 0);
            mt = (g_deg_t[gm] > 0);
        }
        float res[4];
#pragma unroll
        for (int j = 0; j < 4; j++) {
            int gn = n0 + tx * 4 + j;
            float v = acc[i][j];
            if (epi_mode == 1) {
                v += g_bsum[gn];
                if (mu) v += g_bu[gn];
                if (mt) v += g_bl[gn];
            } else if (epi_mode == 2) {
                v += bias_ext[gn];
            }
            if (use_cbuf) v += g_const[(size_t)gm * 384 + coff + gn];
            v *= alpha;
            if (relu) v = fmaxf(v, 0.f);
            res[j] = v;
        }
        *(float4*)(C + (size_t)gm * ldc + n0 + tx * 4) = make_float4(res[0], res[1], res[2], res[3]);
    }
}

// ---------------- launch (pure kernel launches; no other CUDA API) ----------------
extern "C" void kernel_launch(void* const* d_in, const int* in_sizes, int n_in,
                              void* d_out, int out_size) {
    const float* feat_s = (const float*)d_in[0];
    const float* feat_c = (const float*)d_in[1];
    const float* feat_l = (const float*)d_in[2];
    const float* W_fs = (const float*)d_in[3];
    const float* b_fs = (const float*)d_in[4];
    const float* W_fc = (const float*)d_in[5];
    const float* b_fc = (const float*)d_in[6];
    const float* W_fl = (const float*)d_in[7];
    const float* b_fl = (const float*)d_in[8];
    const float* W_self_u = (const float*)d_in[9];
    const float* W_neigh_u = (const float*)d_in[10];
    const float* b_u = (const float*)d_in[11];
    const float* W_self_t = (const float*)d_in[12];
    const float* W_neigh_t = (const float*)d_in[13];
    const float* b_t = (const float*)d_in[14];
    const int* und_src = (const int*)d_in[15];
    const int* und_dst = (const int*)d_in[16];
    const int* tea_src = (const int*)d_in[17];
    const int* tea_dst = (const int*)d_in[18];
    float* out = (float*)d_out;

    // 1 zero, 2 hist, 3 prep, 4 proj (ncu-profiled slot = GEMM kernel)
    zero_deg_kernel<<<(N_C + 255) / 256, 256>>>();
    hist_all_kernel<<<((E_U + E_T) / 4 + 255) / 256, 256>>>((const int4*)und_dst, (const int4*)tea_dst);
    {
        int total = 64 * 384 + 128 * 384 + 384 * 3 + NLAY * HDIM * HDIM;
        prep_kernel<<<(total + 255) / 256, 256>>>(W_fs, b_fs, W_fl, b_fl,
                                                  W_self_u, W_neigh_u, b_u,
                                                  W_self_t, W_neigh_t, b_t);
    }
    {
        dim3 grid((N_C + 127) / 128, HDIM / 64);
        gemm_kernel<<<grid, 256>>>(TAG_EXT, feat_c, D_C,
                                   TAG_EXT, W_fc, 0, HDIM,
                                   TAG_HCA, nullptr, HDIM,
                                   N_C, HDIM, D_C,
                                   /*epi*/2, b_fc,
                                   /*cbuf*/0, 0, 1.f, 0);
    }

    // 5 cvt (before agg), 6-8 scan, 9 scatter
    {
        int total = (N_S * D_S + N_L * D_L) / 4;
        cvt_kernel<<<(total + 255) / 256, 256>>>((const float4*)feat_s, (const float4*)feat_l);
    }
    {
        dim3 g(NBLK, 2);
        scan_part_kernel<<<g, 256>>>();
        scan_mid_kernel<<<1, 32>>>();
        scan_emit_kernel<<<g, 256>>>();
    }
    scatter_all_kernel<<<((E_U + E_T) / 4 + 255) / 256, 256>>>(
        (const int4*)und_src, (const int4*)und_dst, (const int4*)tea_src, (const int4*)tea_dst);

    // 10 agg (fp16 inputs), 11 const, 12-14 layers
    agg_all_kernel<<<(2 * N_C * 32 + 255) / 256, 256>>>();

    {
        dim3 grid((N_C + 127) / 128, 384 / 64);
        gemm_kernel<<<grid, 256>>>(TAG_MF, nullptr, 192,
                                   TAG_WF, nullptr, 0, 384,
                                   TAG_CONST, nullptr, 384,
                                   N_C, 384, 192,
                                   /*epi*/1, nullptr,
                                   /*cbuf*/0, 0, 1.f, 0);
    }

    for (int li = 0; li < NLAY; li++) {
        int a_tag = (li & 1) ? TAG_HCB : TAG_HCA;
        int c_tag = (li == NLAY - 1) ? TAG_EXT : ((li & 1) ? TAG_HCA : TAG_HCB);
        float* c_ext = (li == NLAY - 1) ? out : nullptr;
        float alpha = (li == 0) ? 0.5f : 1.0f;
        int relu = (li < NLAY - 1) ? 1 : 0;
        dim3 grid((N_C + 127) / 128, HDIM / 64);
        gemm_kernel<<<grid, 256>>>(a_tag, nullptr, HDIM,
                                   TAG_WS, nullptr, li * HDIM * HDIM, HDIM,
                                   c_tag, c_ext, HDIM,
                                   N_C, HDIM, HDIM,
                                   /*epi*/0, nullptr,
                                   /*cbuf*/1, li * HDIM,
                                   alpha, relu);
    }
}

// round 13
// speedup vs baseline: 1.1506x; 1.0587x over previous
#include <cuda_runtime.h>
#include <cuda_bf16.h>

#define N_S 100000
#define N_C 20000
#define N_L 5000
#define E_U 2000000
#define E_T 500000
#define D_S 64
#define D_C 32
#define D_L 128
#define HDIM 128
#define NLAY 3

#define SCAN_ELEMS 1024
#define NBLK ((N_C + SCAN_ELEMS - 1) / SCAN_ELEMS)   // 20

// ---------------- scratch (static __device__ allocations only) ----------------
__device__ int   g_deg_u[N_C];
__device__ int   g_deg_t[N_C];
__device__ int   g_rp_u[N_C + 1];
__device__ int   g_rp_t[N_C + 1];
__device__ int   g_cur_u[N_C];
__device__ int   g_cur_t[N_C];
__device__ int   g_csr_u[E_U];
__device__ int   g_csr_t[E_T];
__device__ int   g_blksum[2][NBLK];
__device__ int   g_blkoff[2][NBLK];
__device__ float g_mf[N_C * 192];        // [c][0:64]=mean student feat, [64:192]=mean lecture feat
__device__ float g_Wfused[192 * 384];    // rows 0:64 = W_fs@Wnu_i ; rows 64:192 = W_fl@Wnt_i
__device__ float g_bu[384];              // b_fs @ Wnu_i  (applies when deg_u>0)
__device__ float g_bl[384];              // b_fl @ Wnt_i  (applies when deg_t>0)
__device__ float g_bsum[384];            // b_u[i] + b_t[i]
__device__ float g_Ws[NLAY * HDIM * HDIM];   // W_self_u[i] + W_self_t[i]
__device__ float g_const[N_C * 384];     // per-layer constant terms
__device__ float g_hcA[N_C * HDIM];
__device__ float g_hcB[N_C * HDIM];

// buffer tags (resolved on device; keeps kernel_launch free of cudaGetSymbolAddress)
#define TAG_EXT   0
#define TAG_MF    1
#define TAG_WF    2
#define TAG_CONST 3
#define TAG_HCA   4
#define TAG_HCB   5
#define TAG_WS    6

__device__ __forceinline__ const float* resolve_c(int tag, const float* ext, int off) {
    switch (tag) {
        case TAG_MF:    return g_mf;
        case TAG_WF:    return g_Wfused;
        case TAG_CONST: return g_const;
        case TAG_HCA:   return g_hcA;
        case TAG_HCB:   return g_hcB;
        case TAG_WS:    return g_Ws + off;
        default:        return ext + off;
    }
}
__device__ __forceinline__ float* resolve_m(int tag, float* ext) {
    switch (tag) {
        case TAG_CONST: return g_const;
        case TAG_HCA:   return g_hcA;
        case TAG_HCB:   return g_hcB;
        default:        return ext;
    }
}

// ---------------- CSR build ----------------
__global__ void zero_deg_kernel() {
    int i = blockIdx.x * blockDim.x + threadIdx.x;
    if (i < N_C) { g_deg_u[i] = 0; g_deg_t[i] = 0; }
}

__global__ void hist_all_kernel(const int4* __restrict__ und_dst, const int4* __restrict__ tea_dst) {
    int i = blockIdx.x * blockDim.x + threadIdx.x;
    if (i < E_U / 4) {
        int4 d = und_dst[i];
        atomicAdd(&g_deg_u[d.x], 1);
        atomicAdd(&g_deg_u[d.y], 1);
        atomicAdd(&g_deg_u[d.z], 1);
        atomicAdd(&g_deg_u[d.w], 1);
    } else {
        int j = i - E_U / 4;
        if (j < E_T / 4) {
            int4 d = tea_dst[j];
            atomicAdd(&g_deg_t[d.x], 1);
            atomicAdd(&g_deg_t[d.y], 1);
            atomicAdd(&g_deg_t[d.z], 1);
            atomicAdd(&g_deg_t[d.w], 1);
        }
    }
}

__global__ void scan_part_kernel() {
    int rel = blockIdx.y;
    const int* deg = rel ? g_deg_t : g_deg_u;
    int tid = threadIdx.x;
    int base = blockIdx.x * SCAN_ELEMS + tid * 4;
    int s = 0;
#pragma unroll
    for (int j = 0; j < 4; j++)
        if (base + j < N_C) s += deg[base + j];
    __shared__ int sh[256];
    sh[tid] = s;
    __syncthreads();
    for (int off = 128; off > 0; off >>= 1) {
        if (tid < off) sh[tid] += sh[tid + off];
        __syncthreads();
    }
    if (tid == 0) g_blksum[rel][blockIdx.x] = sh[0];
}

__global__ void scan_mid_kernel() {
    int tid = threadIdx.x;
    if (tid < 2) {
        int run = 0;
        for (int b = 0; b < NBLK; b++) {
            g_blkoff[tid][b] = run;
            run += g_blksum[tid][b];
        }
        if (tid) g_rp_t[N_C] = run; else g_rp_u[N_C] = run;
    }
}

__global__ void scan_emit_kernel() {
    int rel = blockIdx.y;
    const int* deg = rel ? g_deg_t : g_deg_u;
    int* rowptr = rel ? g_rp_t : g_rp_u;
    int* cur = rel ? g_cur_t : g_cur_u;
    int tid = threadIdx.x;
    int base = blockIdx.x * SCAN_ELEMS + tid * 4;
    int v[4];
    int s = 0;
#pragma unroll
    for (int j = 0; j < 4; j++) {
        v[j] = (base + j < N_C) ? deg[base + j] : 0;
        s += v[j];
    }
    __shared__ int sh[256];
    sh[tid] = s;
    __syncthreads();
    for (int off = 1; off < 256; off <<= 1) {
        int t = (tid >= off) ? sh[tid - off] : 0;
        __syncthreads();
        sh[tid] += t;
        __syncthreads();
    }
    int excl = ((tid > 0) ? sh[tid - 1] : 0) + g_blkoff[rel][blockIdx.x];
#pragma unroll
    for (int j = 0; j < 4; j++) {
        if (base + j < N_C) {
            rowptr[base + j] = excl;
            cur[base + j] = excl;
            excl += v[j];
        }
    }
}

__global__ void scatter_all_kernel(const int4* __restrict__ und_src, const int4* __restrict__ und_dst,
                                   const int4* __restrict__ tea_src, const int4* __restrict__ tea_dst) {
    int i = blockIdx.x * blockDim.x + threadIdx.x;
    if (i < E_U / 4) {
        int4 d = und_dst[i];
        int4 s = und_src[i];
        g_csr_u[atomicAdd(&g_cur_u[d.x], 1)] = s.x;
        g_csr_u[atomicAdd(&g_cur_u[d.y], 1)] = s.y;
        g_csr_u[atomicAdd(&g_cur_u[d.z], 1)] = s.z;
        g_csr_u[atomicAdd(&g_cur_u[d.w], 1)] = s.w;
    } else {
        int j = i - E_U / 4;
        if (j < E_T / 4) {
            int4 d = tea_dst[j];
            int4 s = tea_src[j];
            g_csr_t[atomicAdd(&g_cur_t[d.x], 1)] = s.x;
            g_csr_t[atomicAdd(&g_cur_t[d.y], 1)] = s.y;
            g_csr_t[atomicAdd(&g_cur_t[d.z], 1)] = s.z;
            g_csr_t[atomicAdd(&g_cur_t[d.w], 1)] = s.w;
        }
    }
}

// ---------------- aggregation: warp per concept (fp32 features, R10-identical) ----------------
__global__ void agg_all_kernel(const float* __restrict__ feat_s, const float* __restrict__ feat_l) {
    int w = (blockIdx.x * blockDim.x + threadIdx.x) >> 5;
    int lane = threadIdx.x & 31;
    if (w < N_C) {
        int s0 = g_rp_u[w], s1 = g_rp_u[w + 1];
        float2 a0 = {0.f, 0.f}, a1 = {0.f, 0.f}, a2 = {0.f, 0.f}, a3 = {0.f, 0.f};
        int e = s0;
        for (; e + 4 <= s1; e += 4) {
            int i0 = g_csr_u[e], i1 = g_csr_u[e + 1], i2 = g_csr_u[e + 2], i3 = g_csr_u[e + 3];
            float2 v0 = __ldg((const float2*)(feat_s + (size_t)i0 * D_S) + lane);
            float2 v1 = __ldg((const float2*)(feat_s + (size_t)i1 * D_S) + lane);
            float2 v2 = __ldg((const float2*)(feat_s + (size_t)i2 * D_S) + lane);
            float2 v3 = __ldg((const float2*)(feat_s + (size_t)i3 * D_S) + lane);
            a0.x += v0.x; a0.y += v0.y;
            a1.x += v1.x; a1.y += v1.y;
            a2.x += v2.x; a2.y += v2.y;
            a3.x += v3.x; a3.y += v3.y;
        }
        for (; e < s1; e++) {
            int i0 = g_csr_u[e];
            float2 v0 = __ldg((const float2*)(feat_s + (size_t)i0 * D_S) + lane);
            a0.x += v0.x; a0.y += v0.y;
        }
        float sx = a0.x + a1.x + a2.x + a3.x;
        float sy = a0.y + a1.y + a2.y + a3.y;
        float inv = 1.0f / (float)max(s1 - s0, 1);
        g_mf[(size_t)w * 192 + lane * 2 + 0] = sx * inv;
        g_mf[(size_t)w * 192 + lane * 2 + 1] = sy * inv;
    } else if (w < 2 * N_C) {
        int c = w - N_C;
        int s0 = g_rp_t[c], s1 = g_rp_t[c + 1];
        float4 a0 = {0, 0, 0, 0}, a1 = {0, 0, 0, 0};
        int e = s0;
        for (; e + 2 <= s1; e += 2) {
            int i0 = g_csr_t[e], i1 = g_csr_t[e + 1];
            float4 v0 = __ldg((const float4*)(feat_l + (size_t)i0 * D_L) + lane);
            float4 v1 = __ldg((const float4*)(feat_l + (size_t)i1 * D_L) + lane);
            a0.x += v0.x; a0.y += v0.y; a0.z += v0.z; a0.w += v0.w;
            a1.x += v1.x; a1.y += v1.y; a1.z += v1.z; a1.w += v1.w;
        }
        for (; e < s1; e++) {
            int i0 = g_csr_t[e];
            float4 v0 = __ldg((const float4*)(feat_l + (size_t)i0 * D_L) + lane);
            a0.x += v0.x; a0.y += v0.y; a0.z += v0.z; a0.w += v0.w;
        }
        float sx = a0.x + a1.x, sy = a0.y + a1.y, sz = a0.z + a1.z, sw = a0.w + a1.w;
        float inv = 1.0f / (float)max(s1 - s0, 1);
        float* o = g_mf + (size_t)c * 192 + 64 + lane * 4;
        o[0] = sx * inv; o[1] = sy * inv; o[2] = sz * inv; o[3] = sw * inv;
    }
}

// ---------------- fused weight prep (tiny; R10-identical) ----------------
__global__ void prep_kernel(const float* __restrict__ W_fs, const float* __restrict__ b_fs,
                            const float* __restrict__ W_fl, const float* __restrict__ b_fl,
                            const float* __restrict__ Wsu, const float* __restrict__ Wnu,
                            const float* __restrict__ bu_in,
                            const float* __restrict__ Wst, const float* __restrict__ Wnt,
                            const float* __restrict__ bt_in) {
    const int n0 = 64 * 384;
    const int n1 = 128 * 384;
    const int n2 = 384, n3 = 384, n4 = 384;
    const int n5 = NLAY * HDIM * HDIM;
    int idx = blockIdx.x * blockDim.x + threadIdx.x;
    if (idx < n0) {
        int r = idx / 384, c = idx % 384;
        int li = c >> 7, n = c & 127;
        const float* wn = Wnu + li * HDIM * HDIM;
        float s = 0.f;
        for (int k = 0; k < HDIM; k++) s += W_fs[r * HDIM + k] * wn[k * HDIM + n];
        g_Wfused[r * 384 + c] = s;
        return;
    }
    idx -= n0;
    if (idx < n1) {
        int r = idx / 384, c = idx % 384;
        int li = c >> 7, n = c & 127;
        const float* wn = Wnt + li * HDIM * HDIM;
        float s = 0.f;
        for (int k = 0; k < HDIM; k++) s += W_fl[r * HDIM + k] * wn[k * HDIM + n];
        g_Wfused[(64 + r) * 384 + c] = s;
        return;
    }
    idx -= n1;
    if (idx < n2) {
        int li = idx >> 7, n = idx & 127;
        const float* wn = Wnu + li * HDIM * HDIM;
        float s = 0.f;
        for (int k = 0; k < HDIM; k++) s += b_fs[k] * wn[k * HDIM + n];
        g_bu[idx] = s;
        return;
    }
    idx -= n2;
    if (idx < n3) {
        int li = idx >> 7, n = idx & 127;
        const float* wn = Wnt + li * HDIM * HDIM;
        float s = 0.f;
        for (int k = 0; k < HDIM; k++) s += b_fl[k] * wn[k * HDIM + n];
        g_bl[idx] = s;
        return;
    }
    idx -= n3;
    if (idx < n4) {
        g_bsum[idx] = bu_in[idx] + bt_in[idx];
        return;
    }
    idx -= n4;
    if (idx < n5) {
        g_Ws[idx] = Wsu[idx] + Wst[idx];
        return;
    }
}

// ---------------- tiled SIMT GEMM v3: 64x64 tile, 128 threads, 8x4/thread ----------------
// Half-size blocks vs R10: ~9.1K regs/block -> ~7 blocks/SM (occ ~58% vs 27%),
// grid doubles (626+ blocks) for better latency hiding on the measured issue=52% profile.
__global__ __launch_bounds__(128) void gemm_kernel(
    int a_tag, const float* a_ext, int lda,
    int b_tag, const float* b_ext, int b_off, int ldb,
    int c_tag, float* c_ext, int ldc,
    int M, int N, int K,
    int epi_mode, const float* bias_ext,
    int use_cbuf, int coff,
    float alpha, int relu) {
    const float* A = resolve_c(a_tag, a_ext, 0);
    const float* B = resolve_c(b_tag, b_ext, b_off);
    float* C = resolve_m(c_tag, c_ext);

    __shared__ float As[8][68];
    __shared__ float Bs[8][68];
    int tid = threadIdx.x;
    int m0 = blockIdx.x * 64;
    int n0 = blockIdx.y * 64;
    int tx = tid & 15;   // 16 col groups * 4
    int ty = tid >> 4;   // 8 row groups * 8

    float acc[8][4];
#pragma unroll
    for (int i = 0; i < 8; i++)
#pragma unroll
        for (int j = 0; j < 4; j++) acc[i][j] = 0.f;

    int la_row = tid >> 1;        // 0..63
    int la_k = (tid & 1) * 4;     // 0 or 4
    int lb_k = tid >> 4;          // 0..7
    int lb_n = (tid & 15) * 4;    // 0..60

    for (int k0 = 0; k0 < K; k0 += 8) {
        float4 av = {0.f, 0.f, 0.f, 0.f};
        int gm = m0 + la_row;
        if (gm < M) av = *(const float4*)(A + (size_t)gm * lda + k0 + la_k);
        As[la_k + 0][la_row] = av.x;
        As[la_k + 1][la_row] = av.y;
        As[la_k + 2][la_row] = av.z;
        As[la_k + 3][la_row] = av.w;
        float4 bv = *(const float4*)(B + (size_t)(k0 + lb_k) * ldb + n0 + lb_n);
        *(float4*)&Bs[lb_k][lb_n] = bv;
        __syncthreads();
#pragma unroll
        for (int kk = 0; kk < 8; kk++) {
            float4 a0 = *(const float4*)&As[kk][ty * 8];
            float4 a1 = *(const float4*)&As[kk][ty * 8 + 4];
            float4 b = *(const float4*)&Bs[kk][tx * 4];
            float a[8] = {a0.x, a0.y, a0.z, a0.w, a1.x, a1.y, a1.z, a1.w};
            float bb[4] = {b.x, b.y, b.z, b.w};
#pragma unroll
            for (int i = 0; i < 8; i++)
#pragma unroll
                for (int j = 0; j < 4; j++) acc[i][j] += a[i] * bb[j];
        }
        __syncthreads();
    }

#pragma unroll
    for (int i = 0; i < 8; i++) {
        int gm = m0 + ty * 8 + i;
        if (gm >= M) break;
        bool mu = false, mt = false;
        if (epi_mode == 1) {
            mu = (g_deg_u[gm] > 0);
            mt = (g_deg_t[gm] > 0);
        }
        float res[4];
#pragma unroll
        for (int j = 0; j < 4; j++) {
            int gn = n0 + tx * 4 + j;
            float v = acc[i][j];
            if (epi_mode == 1) {
                v += g_bsum[gn];
                if (mu) v += g_bu[gn];
                if (mt) v += g_bl[gn];
            } else if (epi_mode == 2) {
                v += bias_ext[gn];
            }
            if (use_cbuf) v += g_const[(size_t)gm * 384 + coff + gn];
            v *= alpha;
            if (relu) v = fmaxf(v, 0.f);
            res[j] = v;
        }
        *(float4*)(C + (size_t)gm * ldc + n0 + tx * 4) = make_float4(res[0], res[1], res[2], res[3]);
    }
}

// ---------------- launch (pure kernel launches; no other CUDA API) ----------------
extern "C" void kernel_launch(void* const* d_in, const int* in_sizes, int n_in,
                              void* d_out, int out_size) {
    const float* feat_s = (const float*)d_in[0];
    const float* feat_c = (const float*)d_in[1];
    const float* feat_l = (const float*)d_in[2];
    const float* W_fs = (const float*)d_in[3];
    const float* b_fs = (const float*)d_in[4];
    const float* W_fc = (const float*)d_in[5];
    const float* b_fc = (const float*)d_in[6];
    const float* W_fl = (const float*)d_in[7];
    const float* b_fl = (const float*)d_in[8];
    const float* W_self_u = (const float*)d_in[9];
    const float* W_neigh_u = (const float*)d_in[10];
    const float* b_u = (const float*)d_in[11];
    const float* W_self_t = (const float*)d_in[12];
    const float* W_neigh_t = (const float*)d_in[13];
    const float* b_t = (const float*)d_in[14];
    const int* und_src = (const int*)d_in[15];
    const int* und_dst = (const int*)d_in[16];
    const int* tea_src = (const int*)d_in[17];
    const int* tea_dst = (const int*)d_in[18];
    float* out = (float*)d_out;

    const int MT64 = (N_C + 63) / 64;   // 313 row tiles

    // 1 zero, 2 hist, 3 prep, 4 proj (ncu-profiled slot = new GEMM)
    zero_deg_kernel<<<(N_C + 255) / 256, 256>>>();
    hist_all_kernel<<<((E_U + E_T) / 4 + 255) / 256, 256>>>((const int4*)und_dst, (const int4*)tea_dst);
    {
        int total = 64 * 384 + 128 * 384 + 384 * 3 + NLAY * HDIM * HDIM;
        prep_kernel<<<(total + 255) / 256, 256>>>(W_fs, b_fs, W_fl, b_fl,
                                                  W_self_u, W_neigh_u, b_u,
                                                  W_self_t, W_neigh_t, b_t);
    }
    {
        dim3 grid(MT64, HDIM / 64);
        gemm_kernel<<<grid, 128>>>(TAG_EXT, feat_c, D_C,
                                   TAG_EXT, W_fc, 0, HDIM,
                                   TAG_HCA, nullptr, HDIM,
                                   N_C, HDIM, D_C,
                                   /*epi*/2, b_fc,
                                   /*cbuf*/0, 0, 1.f, 0);
    }

    // 5-7 scan, 8 scatter, 9 agg
    {
        dim3 g(NBLK, 2);
        scan_part_kernel<<<g, 256>>>();
        scan_mid_kernel<<<1, 32>>>();
        scan_emit_kernel<<<g, 256>>>();
    }
    scatter_all_kernel<<<((E_U + E_T) / 4 + 255) / 256, 256>>>(
        (const int4*)und_src, (const int4*)und_dst, (const int4*)tea_src, (const int4*)tea_dst);

    agg_all_kernel<<<(2 * N_C * 32 + 255) / 256, 256>>>(feat_s, feat_l);

    // 10 const: const[20000,384] = mf @ Wfused + masked biases + bsum
    {
        dim3 grid(MT64, 384 / 64);
        gemm_kernel<<<grid, 128>>>(TAG_MF, nullptr, 192,
                                   TAG_WF, nullptr, 0, 384,
                                   TAG_CONST, nullptr, 384,
                                   N_C, 384, 192,
                                   /*epi*/1, nullptr,
                                   /*cbuf*/0, 0, 1.f, 0);
    }

    // 11-13 layers: hc_next = act(alpha_i * (hc @ Ws_i + const_i))
    for (int li = 0; li < NLAY; li++) {
        int a_tag = (li & 1) ? TAG_HCB : TAG_HCA;
        int c_tag = (li == NLAY - 1) ? TAG_EXT : ((li & 1) ? TAG_HCA : TAG_HCB);
        float* c_ext = (li == NLAY - 1) ? out : nullptr;
        float alpha = (li == 0) ? 0.5f : 1.0f;
        int relu = (li < NLAY - 1) ? 1 : 0;
        dim3 grid(MT64, HDIM / 64);
        gemm_kernel<<<grid, 128>>>(a_tag, nullptr, HDIM,
                                   TAG_WS, nullptr, li * HDIM * HDIM, HDIM,
                                   c_tag, c_ext, HDIM,
                                   N_C, HDIM, HDIM,
                                   /*epi*/0, nullptr,
                                   /*cbuf*/1, li * HDIM,
                                   alpha, relu);
    }
}